// round 11
// baseline (speedup 1.0000x reference)
#include <cuda_runtime.h>

// NonMaximaSuppression2d: x (8,32,512,512) fp32.
// m = max over 8 neighbors (replicate pad), floored at 0 (zeroed center tap).
// out = x * (x > m).
// R10: keep R9's 6-row front-batch (MLP~6, launch_bounds(128,12)); replace the
// per-lane strided edge-scalar loads (each ~5 L1 wavefronts, ~3.5x wavefront
// inflation -> L1 61% while DRAM 80%) with compute-phase warp shuffles on the
// loaded vectors; only lanes 0/31 do a predicated JIT L1-hit scalar load.

#define HH 512
#define WW 512
#define RPT 4           // rows per output strip
#define NROWS (RPT + 2) // 6 rows in the window
#define TPB 128         // threads per block = WW/4 float4 groups

__device__ __forceinline__ int clampy(int y) { return min(max(y, 0), HH - 1); }

// horizontal halo for one row: neighbor-lane values via shuffle; warp-boundary
// lanes fix up with a scalar load (L1 hit: the block loaded the whole row).
__device__ __forceinline__ void halo(const float* __restrict__ in, int y, int c,
                                     int lane, const float4& v,
                                     float& l, float& r) {
    l = __shfl_up_sync(0xffffffffu, v.w, 1);
    r = __shfl_down_sync(0xffffffffu, v.x, 1);
    const float* p = in + (size_t)clampy(y) * WW + c;
    if (lane == 0)  l = (c > 0)      ? __ldg(p - 1) : v.x;
    if (lane == 31) r = (c + 4 < WW) ? __ldg(p + 4) : v.w;
}

// max of 3 horizontally adjacent values per lane (rows above/below)
__device__ __forceinline__ float4 hmax3(const float4& v, float l, float r) {
    float4 h;
    h.x = fmaxf(fmaxf(l,   v.x), v.y);
    h.y = fmaxf(fmaxf(v.x, v.y), v.z);
    h.z = fmaxf(fmaxf(v.y, v.z), v.w);
    h.w = fmaxf(fmaxf(v.z, v.w), r);
    return h;
}

// max of the 2 horizontal neighbors (center excluded; for the center row)
__device__ __forceinline__ float4 hmax2(const float4& v, float l, float r) {
    float4 h;
    h.x = fmaxf(l,   v.y);
    h.y = fmaxf(v.x, v.z);
    h.z = fmaxf(v.y, v.w);
    h.w = fmaxf(v.z, r);
    return h;
}

__global__ __launch_bounds__(TPB, 12)
void nms2d_kernel(const float* __restrict__ x, float* __restrict__ out) {
    const int tiles_per_img = HH / RPT;             // 128
    const int img  = blockIdx.x / tiles_per_img;
    const int tile = blockIdx.x % tiles_per_img;

    const float* in = x   + (size_t)img * HH * WW;
    float*       o  = out + (size_t)img * HH * WW;

    const int c    = threadIdx.x * 4;               // 0..508
    const int lane = threadIdx.x & 31;
    const int y0   = tile * RPT;

    // front-batch the 6-row window: 6 independent LDG.128, nothing else
    float4 v[NROWS];
    #pragma unroll
    for (int k = 0; k < NROWS; k++)
        v[k] = *reinterpret_cast<const float4*>(
            in + (size_t)clampy(y0 - 1 + k) * WW + c);

    float* op = o + (size_t)y0 * WW + c;

    #pragma unroll
    for (int i = 0; i < RPT; i++) {
        float lp, rp, lc, rc, ln, rn;
        halo(in, y0 - 1 + i,     c, lane, v[i],     lp, rp);
        halo(in, y0 + i,         c, lane, v[i + 1], lc, rc);
        halo(in, y0 + i + 1,     c, lane, v[i + 2], ln, rn);

        float4 mp = hmax3(v[i],     lp, rp);
        float4 mc = hmax2(v[i + 1], lc, rc);
        float4 mn = hmax3(v[i + 2], ln, rn);

        // fold the zeroed-center-tap floor (reference inits max at 0)
        float4 m;
        m.x = fmaxf(fmaxf(fmaxf(mp.x, mc.x), mn.x), 0.0f);
        m.y = fmaxf(fmaxf(fmaxf(mp.y, mc.y), mn.y), 0.0f);
        m.z = fmaxf(fmaxf(fmaxf(mp.z, mc.z), mn.z), 0.0f);
        m.w = fmaxf(fmaxf(fmaxf(mp.w, mc.w), mn.w), 0.0f);

        float4 xc = v[i + 1];
        float4 r;
        r.x = (xc.x > m.x) ? xc.x : 0.0f;
        r.y = (xc.y > m.y) ? xc.y : 0.0f;
        r.z = (xc.z > m.z) ? xc.z : 0.0f;
        r.w = (xc.w > m.w) ? xc.w : 0.0f;

        *reinterpret_cast<float4*>(op) = r;
        op += WW;
    }
}

extern "C" void kernel_launch(void* const* d_in, const int* in_sizes, int n_in,
                              void* d_out, int out_size) {
    const float* x = (const float*)d_in[0];
    float* out = (float*)d_out;

    const int n_img = in_sizes[0] / (HH * WW);      // B*C = 256
    const int blocks = n_img * (HH / RPT);          // 32768

    nms2d_kernel<<<blocks, TPB>>>(x, out);
}